// round 12
// baseline (speedup 1.0000x reference)
#include <cuda_runtime.h>
#include <cuda_fp16.h>
#include <cstdint>

#define C_IN   128
#define C_OUT  256
#define HH     56
#define WW     56
#define HW     3136
#define NPIX   100352
#define KTOT   1152          // 9 taps * 128 cin (tap-major k)
#define BM     64            // couts per CTA
#define BN     128           // pixels per CTA
#define KTILES 72
#define TPB    128
#define STAGES 8

// smem: B only. [pixel(128)][8 words] (32B/pixel, fp16)
#define STG_WORDS   1024
#define SMEM_BYTES  (STAGES*STG_WORDS*4)     // 32768

#define TWA_WORDS   (2*KTILES*1024)          // 147456 (each word = 2 fp16)
#define TWA_BLOCKS  (TWA_WORDS/256)          // 576
#define TIN_BLOCKS  (98*4*32)
#define PREP_BLOCKS (TWA_BLOCKS + TIN_BLOCKS)

// scratch: A fragment-native fp16 (packed pairs), input NHWC fp16 pair-permuted
__device__ uint32_t g_wa[TWA_WORDS];                 // 0.59 MB
__device__ __half   g_in2h[(size_t)NPIX*C_IN];       // 25.7 MB

// merged prepass (unchanged from R11)
__global__ void prep(const float* __restrict__ f, const float* __restrict__ in) {
    __shared__ float t[32][33];
    if (blockIdx.x < TWA_BLOCKS) {
        // A: word = (by*KT+kt)*1024 + mf*128 + lane*4 + reg
        int idx  = blockIdx.x * 256 + threadIdx.x;
        int reg  = idx & 3;
        int lane = (idx >> 2) & 31;
        int mf   = (idx >> 7) & 7;
        int r10  = idx >> 10;
        int kt   = r10 % KTILES;
        int by   = r10 / KTILES;
        int cout = by*128 + mf*16 + (lane >> 2) + 8*(reg & 1);
        int k0   = kt*16 + (lane & 3)*2 + 8*(reg >> 1);
        int tap  = k0 >> 7, cin = k0 & 127;
        float lo = f[(cout*C_IN + cin)*9 + tap];
        float hi = f[(cout*C_IN + cin + 1)*9 + tap];
        __half2 h = __floats2half2_rn(lo, hi);
        g_wa[idx] = *reinterpret_cast<uint32_t*>(&h);
    } else {
        // B: NCHW -> per-pixel [128 fp16], per-16-group pair permutation
        int bid = blockIdx.x - TWA_BLOCKS;
        const int hwb = bid % 98;
        const int cb  = (bid / 98) % 4;
        const int n   = bid / (98 * 4);
        const int hw0 = hwb * 32, c0 = cb * 32;
        const int tx = threadIdx.x & 31, ty = threadIdx.x >> 5;
        const float* p = in + ((size_t)n*C_IN + c0)*HW + hw0;
        #pragma unroll
        for (int i = 0; i < 4; ++i)
            t[ty + 8*i][tx] = p[(size_t)(ty + 8*i)*HW + tx];
        __syncthreads();
        const int k = tx & 15;
        const int posloc = (tx & 16) + 4*((k & 7) >> 1) + 2*((k >> 3) & 1) + (k & 1);
        #pragma unroll
        for (int i = 0; i < 4; ++i) {
            int pix = ty + 8*i;
            g_in2h[((size_t)(n*HW + hw0 + pix))*C_IN + c0 + posloc] =
                __float2half_rn(t[tx][pix]);
        }
    }
}

__device__ __forceinline__ uint32_t s2u(const void* p) {
    uint32_t a;
    asm("{ .reg .u64 t; cvta.to.shared.u64 t, %1; cvt.u32.u64 %0, t; }" : "=r"(a) : "l"(p));
    return a;
}
__device__ __forceinline__ void cp16(uint32_t dst, const void* src, uint32_t sz) {
    asm volatile("cp.async.cg.shared.global [%0], [%1], 16, %2;"
                 :: "r"(dst), "l"(src), "r"(sz));
}
__device__ __forceinline__ void mma16816(float* d, const uint32_t* a,
                                         uint32_t b0, uint32_t b1) {
    asm volatile(
        "mma.sync.aligned.m16n8k16.row.col.f32.f16.f16.f32 "
        "{%0,%1,%2,%3}, {%4,%5,%6,%7}, {%8,%9}, {%0,%1,%2,%3};"
        : "+f"(d[0]), "+f"(d[1]), "+f"(d[2]), "+f"(d[3])
        : "r"(a[0]), "r"(a[1]), "r"(a[2]), "r"(a[3]), "r"(b0), "r"(b1));
}

__global__ __launch_bounds__(TPB, 4)
void conv_mma(const float* __restrict__ bias, float* __restrict__ out) {
    extern __shared__ uint32_t sm[];
    const uint32_t sb = s2u(sm);
    const int tid  = threadIdx.x;
    const int warp = tid >> 5;
    const int lane = tid & 31;
    const int bx   = blockIdx.x;   // pixel block (784)
    const int by4  = blockIdx.y;   // cout block of 64 (4)

    // ---- B copy: thread = pixel, two 16B chunks ----
    const int pix = bx * BN + tid;
    const int n   = pix / HW;
    const int hw  = pix - n * HW;
    const int h   = hw / WW;
    const int w   = hw - h * WW;
    const uint32_t bdst = tid * 32;

    // ---- consumer: 4 warps, 2m x 2n, warp tile 32x64 ----
    const int wm = warp >> 1, wn = warp & 1;
    // A fragment base: by = by4>>1 selects 128-cout half, (by4&1)*4 selects mf quad
    const uint32_t* a_gm = g_wa + (size_t)(by4 >> 1) * (KTILES * 1024)
                         + ((by4 & 1) * 4 + wm * 2) * 128 + lane * 4;

    float acc[2][8][4];
    #pragma unroll
    for (int i = 0; i < 2; ++i)
        #pragma unroll
        for (int j = 0; j < 8; ++j)
            #pragma unroll
            for (int q = 0; q < 4; ++q) acc[i][j][q] = 0.f;

    auto issue_copy = [&](int kt, int stg) {
        const uint32_t s0 = sb + stg * (STG_WORDS * 4);
        const int tap = kt >> 3;
        const int t3  = tap / 3;
        const int dh  = t3 - 1, dw = tap - t3 * 3 - 1;
        const bool v = ((unsigned)(h + dh) < HH) && ((unsigned)(w + dw) < WW);
        const uint32_t sz = v ? 16u : 0u;
        const int coff = (kt & 7) * 16;
        const __half* src = g_in2h + (size_t)(pix + dh * WW + dw) * C_IN + coff;
        cp16(s0 + bdst,      src,     sz);
        cp16(s0 + bdst + 16, src + 8, sz);
    };

    #pragma unroll
    for (int s = 0; s < STAGES - 1; ++s) {
        issue_copy(s, s);
        asm volatile("cp.async.commit_group;" ::: "memory");
    }

    // prefetch A fragments for tile 0 (one uint4 per m-frag = full k16)
    uint4 aN[2];
    #pragma unroll
    for (int i = 0; i < 2; ++i)
        aN[i] = *reinterpret_cast<const uint4*>(a_gm + i * 128);

    const int b_off = (wn * 64 + (lane >> 2)) * 8 + (lane & 3) * 2;

    int stg = 0;
    for (int kt = 0; kt < KTILES; ++kt) {
        asm volatile("cp.async.wait_group 6;" ::: "memory");
        __syncthreads();

        uint32_t aw[2][4];
        #pragma unroll
        for (int i = 0; i < 2; ++i) {
            aw[i][0] = aN[i].x; aw[i][1] = aN[i].y;
            aw[i][2] = aN[i].z; aw[i][3] = aN[i].w;
        }
        if (kt + 1 < KTILES) {
            const uint32_t* ap = a_gm + (size_t)(kt + 1) * 1024;
            #pragma unroll
            for (int i = 0; i < 2; ++i)
                aN[i] = *reinterpret_cast<const uint4*>(ap + i * 128);
        }

        const uint32_t* s = sm + stg * STG_WORDS;
        #pragma unroll
        for (int j = 0; j < 8; ++j) {
            uint2 bv = *reinterpret_cast<const uint2*>(s + b_off + j * 64);
            mma16816(acc[0][j], aw[0], bv.x, bv.y);
            mma16816(acc[1][j], aw[1], bv.x, bv.y);
        }

        if (kt + STAGES - 1 < KTILES) {
            int ns = stg + STAGES - 1;
            if (ns >= STAGES) ns -= STAGES;
            issue_copy(kt + STAGES - 1, ns);
        }
        asm volatile("cp.async.commit_group;" ::: "memory");
        if (++stg == STAGES) stg = 0;
    }

    // ---- epilogue: bias + float2 stores ----
    const int eg = lane >> 2, et = lane & 3;
    #pragma unroll
    for (int i = 0; i < 2; ++i) {
        const int cout0 = by4 * BM + wm * 32 + i * 16 + eg;
        const float bz0 = bias[cout0];
        const float bz1 = bias[cout0 + 8];
        #pragma unroll
        for (int j = 0; j < 8; ++j) {
            const int pj  = bx * BN + wn * 64 + j * 8;       // 8-aligned, HW%8==0
            const int n2  = pj / HW;
            const int hw2 = pj - n2 * HW + et * 2;
            float2 v0 = make_float2(acc[i][j][0] + bz0, acc[i][j][1] + bz0);
            float2 v1 = make_float2(acc[i][j][2] + bz1, acc[i][j][3] + bz1);
            *reinterpret_cast<float2*>(out + ((size_t)(n2 * C_OUT + cout0))     * HW + hw2) = v0;
            *reinterpret_cast<float2*>(out + ((size_t)(n2 * C_OUT + cout0 + 8)) * HW + hw2) = v1;
        }
    }
}

extern "C" void kernel_launch(void* const* d_in, const int* in_sizes, int n_in,
                              void* d_out, int out_size) {
    const float* in   = (const float*)d_in[0];
    const float* fl   = (const float*)d_in[1];
    const float* bias = (const float*)d_in[2];
    float* out        = (float*)d_out;

    prep<<<PREP_BLOCKS, 256>>>(fl, in);
    dim3 grid(NPIX / BN, C_OUT / BM);
    conv_mma<<<grid, TPB, SMEM_BYTES>>>(bias, out);
}

// round 13
// speedup vs baseline: 1.5081x; 1.5081x over previous
#include <cuda_runtime.h>
#include <cuda_fp16.h>
#include <cstdint>

#define C_IN   128
#define C_OUT  256
#define HH     56
#define WW     56
#define HW     3136
#define NPIX   100352
#define KTOT   1152          // 9 taps * 128 cin (tap-major k)
#define BM     128
#define BN     128
#define KSTEPS 72            // k16 steps
#define NSTG   18            // stages of 4 ksteps
#define TPB    256
#define SBUF   4             // smem stage buffers

// smem: [buf(4)][kstep(4)][pixel(128)][8 words]  (4KB per kstep slab)
#define STG_WORDS   4096     // words per buf (4 ksteps)
#define SMEM_BYTES  (SBUF*STG_WORDS*4)       // 65536

#define TWA_WORDS   (2*KSTEPS*1024)
#define TWA_BLOCKS  (TWA_WORDS/256)          // 576
#define TIN_BLOCKS  (98*4*32)
#define PREP_BLOCKS (TWA_BLOCKS + TIN_BLOCKS)

__device__ uint32_t g_wa[TWA_WORDS];                 // A fragment-native fp16
__device__ __half   g_in2h[(size_t)NPIX*C_IN];       // input NHWC fp16 permuted

// merged prepass (same as R11)
__global__ void prep(const float* __restrict__ f, const float* __restrict__ in) {
    __shared__ float t[32][33];
    if (blockIdx.x < TWA_BLOCKS) {
        int idx  = blockIdx.x * 256 + threadIdx.x;
        int reg  = idx & 3;
        int lane = (idx >> 2) & 31;
        int mf   = (idx >> 7) & 7;
        int r10  = idx >> 10;
        int kt   = r10 % KSTEPS;
        int by   = r10 / KSTEPS;
        int cout = by*128 + mf*16 + (lane >> 2) + 8*(reg & 1);
        int k0   = kt*16 + (lane & 3)*2 + 8*(reg >> 1);
        int tap  = k0 >> 7, cin = k0 & 127;
        float lo = f[(cout*C_IN + cin)*9 + tap];
        float hi = f[(cout*C_IN + cin + 1)*9 + tap];
        __half2 h = __floats2half2_rn(lo, hi);
        g_wa[idx] = *reinterpret_cast<uint32_t*>(&h);
    } else {
        int bid = blockIdx.x - TWA_BLOCKS;
        const int hwb = bid % 98;
        const int cb  = (bid / 98) % 4;
        const int n   = bid / (98 * 4);
        const int hw0 = hwb * 32, c0 = cb * 32;
        const int tx = threadIdx.x & 31, ty = threadIdx.x >> 5;
        const float* p = in + ((size_t)n*C_IN + c0)*HW + hw0;
        #pragma unroll
        for (int i = 0; i < 4; ++i)
            t[ty + 8*i][tx] = p[(size_t)(ty + 8*i)*HW + tx];
        __syncthreads();
        const int k = tx & 15;
        const int posloc = (tx & 16) + 4*((k & 7) >> 1) + 2*((k >> 3) & 1) + (k & 1);
        #pragma unroll
        for (int i = 0; i < 4; ++i) {
            int pix = ty + 8*i;
            g_in2h[((size_t)(n*HW + hw0 + pix))*C_IN + c0 + posloc] =
                __float2half_rn(t[tx][pix]);
        }
    }
}

__device__ __forceinline__ uint32_t s2u(const void* p) {
    uint32_t a;
    asm("{ .reg .u64 t; cvta.to.shared.u64 t, %1; cvt.u32.u64 %0, t; }" : "=r"(a) : "l"(p));
    return a;
}
__device__ __forceinline__ void cp16(uint32_t dst, const void* src, uint32_t sz) {
    asm volatile("cp.async.cg.shared.global [%0], [%1], 16, %2;"
                 :: "r"(dst), "l"(src), "r"(sz));
}
__device__ __forceinline__ void mma16816(float* d, const uint4& a,
                                         uint32_t b0, uint32_t b1) {
    asm volatile(
        "mma.sync.aligned.m16n8k16.row.col.f32.f16.f16.f32 "
        "{%0,%1,%2,%3}, {%4,%5,%6,%7}, {%8,%9}, {%0,%1,%2,%3};"
        : "+f"(d[0]), "+f"(d[1]), "+f"(d[2]), "+f"(d[3])
        : "r"(a.x), "r"(a.y), "r"(a.z), "r"(a.w), "r"(b0), "r"(b1));
}

__global__ __launch_bounds__(TPB, 2)
void conv_mma(const float* __restrict__ bias, float* __restrict__ out) {
    extern __shared__ uint32_t sm[];
    const uint32_t sb = s2u(sm);
    const int tid  = threadIdx.x;
    const int warp = tid >> 5;
    const int lane = tid & 31;
    const int bx   = blockIdx.x;   // pixel block (784)
    const int by   = blockIdx.y;   // cout block (2)

    // ---- B copy: thread = (pixel tid>>1, 16B chunk tid&1) ----
    const int p0  = tid >> 1;
    const int kq  = tid & 1;
    const int pix = bx * BN + p0;
    const int n   = pix / HW;
    const int hw  = pix - n * HW;
    const int h   = hw / WW;
    const int w   = hw - h * WW;
    const uint32_t bdst = (uint32_t)tid * 16;

    // ---- consumer: 8 warps, 4m x 2n, warp tile 32x64 ----
    const int wm = warp >> 1, wn = warp & 1;
    const uint32_t* a_gm = g_wa + (size_t)by * (KSTEPS * 1024) + (wm * 2) * 128 + lane * 4;

    float acc[2][8][4];
    #pragma unroll
    for (int i = 0; i < 2; ++i)
        #pragma unroll
        for (int j = 0; j < 8; ++j)
            #pragma unroll
            for (int q = 0; q < 4; ++q) acc[i][j][q] = 0.f;

    // copy all 4 ksteps of one stage
    auto issue_stage = [&](int st) {
        const int slot = st & (SBUF - 1);
        #pragma unroll
        for (int s = 0; s < 4; ++s) {
            const int g   = st * 4 + s;
            const uint32_t d0 = sb + (uint32_t)slot * (STG_WORDS * 4) + s * 4096 + bdst;
            const int tap = g >> 3;
            const int t3  = tap / 3;
            const int dh  = t3 - 1, dw = tap - t3 * 3 - 1;
            const bool v = ((unsigned)(h + dh) < HH) && ((unsigned)(w + dw) < WW);
            const int coff = (g & 7) * 16 + kq * 8;
            const __half* src = g_in2h + (size_t)(pix + dh * WW + dw) * C_IN + coff;
            cp16(d0, src, v ? 16u : 0u);
        }
    };

    #pragma unroll
    for (int st = 0; st < SBUF - 1; ++st) {
        issue_stage(st);
        asm volatile("cp.async.commit_group;" ::: "memory");
    }

    // A register ring, prefetch distance 2 (ksteps 0 and 1)
    uint4 abuf[2][2];   // [parity][m-frag]
    #pragma unroll
    for (int i = 0; i < 2; ++i) {
        abuf[0][i] = *reinterpret_cast<const uint4*>(a_gm + i * 128);
        abuf[1][i] = *reinterpret_cast<const uint4*>(a_gm + 1024 + i * 128);
    }

    const int b_off = (wn * 64 + (lane >> 2)) * 8 + (lane & 3) * 2;

    for (int st = 0; st < NSTG; ++st) {
        asm volatile("cp.async.wait_group 2;" ::: "memory");
        __syncthreads();
        const uint32_t* sbase = sm + (st & (SBUF - 1)) * STG_WORDS;

        #pragma unroll
        for (int s = 0; s < 4; ++s) {
            const int g = st * 4 + s;
            const uint32_t* ss = sbase + s * 1024;
            uint2 bv[8];
            #pragma unroll
            for (int j = 0; j < 8; ++j)
                bv[j] = *reinterpret_cast<const uint2*>(ss + b_off + j * 64);
            #pragma unroll
            for (int j = 0; j < 8; ++j) {
                mma16816(acc[0][j], abuf[s & 1][0], bv[j].x, bv[j].y);
                mma16816(acc[1][j], abuf[s & 1][1], bv[j].x, bv[j].y);
            }
            // prefetch A kstep g+2 into the buffer just freed
            if (g + 2 < KSTEPS) {
                const uint32_t* ap = a_gm + (size_t)(g + 2) * 1024;
                #pragma unroll
                for (int i = 0; i < 2; ++i)
                    abuf[s & 1][i] = *reinterpret_cast<const uint4*>(ap + i * 128);
            }
        }

        if (st + SBUF - 1 < NSTG)
            issue_stage(st + SBUF - 1);
        asm volatile("cp.async.commit_group;" ::: "memory");
    }

    // ---- epilogue: bias + float2 stores ----
    const int eg = lane >> 2, et = lane & 3;
    #pragma unroll
    for (int i = 0; i < 2; ++i) {
        const int cout0 = by * BM + wm * 32 + i * 16 + eg;
        const float bz0 = bias[cout0];
        const float bz1 = bias[cout0 + 8];
        #pragma unroll
        for (int j = 0; j < 8; ++j) {
            const int pj  = bx * BN + wn * 64 + j * 8;       // 8-aligned, HW%8==0
            const int n2  = pj / HW;
            const int hw2 = pj - n2 * HW + et * 2;
            float2 v0 = make_float2(acc[i][j][0] + bz0, acc[i][j][1] + bz0);
            float2 v1 = make_float2(acc[i][j][2] + bz1, acc[i][j][3] + bz1);
            *reinterpret_cast<float2*>(out + ((size_t)(n2 * C_OUT + cout0))     * HW + hw2) = v0;
            *reinterpret_cast<float2*>(out + ((size_t)(n2 * C_OUT + cout0 + 8)) * HW + hw2) = v1;
        }
    }
}

extern "C" void kernel_launch(void* const* d_in, const int* in_sizes, int n_in,
                              void* d_out, int out_size) {
    const float* in   = (const float*)d_in[0];
    const float* fl   = (const float*)d_in[1];
    const float* bias = (const float*)d_in[2];
    float* out        = (float*)d_out;

    cudaFuncSetAttribute(conv_mma, cudaFuncAttributeMaxDynamicSharedMemorySize, SMEM_BYTES);

    prep<<<PREP_BLOCKS, 256>>>(fl, in);
    dim3 grid(NPIX / BN, C_OUT / BM);
    conv_mma<<<grid, TPB, SMEM_BYTES>>>(bias, out);
}